// round 16
// baseline (speedup 1.0000x reference)
#include <cuda_runtime.h>
#include <cuda_bf16.h>
#include <cuda_fp16.h>
#include <cstdint>

#define N 4096
#define D 256
#define C 1000
#define BI 256
#define BJ 128
#define NTJ (N / BJ)                // 32 col tiles
#define NTILES 272                  // sum over bi2 of (32 - 2*bi2)
#define NCHUNK 4                    // 4 chunks of 64 k per phase
#define THREADS 256

#define PREP_BLOCKS (6 * N * D / 16 / 256)   // 6144
#define LABEL_BLOCKS 512

#define PITCH_U 36                  // u32 per smem tile row (32 data + 4 pad)
#define PITCH_B (PITCH_U * 4)       // 144 bytes
#define A_TILE_U (BI * PITCH_U)     // 9216 u32
#define B_TILE_U (BJ * PITCH_U)     // 4608 u32
#define STAGE_U (A_TILE_U + B_TILE_U)

// Shared memory layout (32-bit words)
#define OFF_DPH   0                           // 64*256 u32 (dP parked as f16x2)
#define OFF_TILES 16384                       // 2 stages x (A+B) = 27648 u32
#define OFF_SQ    (OFF_TILES + 2 * STAGE_U)   // 768 f32
#define OFF_SRED  (OFF_SQ + 768)
#define SMEM_WORDS (OFF_SRED + 8)
#define SMEM_BYTES (SMEM_WORDS * 4)           // 179,232 B

// Persistent device state; zero at the start of every call (static zero-init;
// the finishing pair block resets after producing the output).
__device__ double g_acc[4];
__device__ unsigned int g_cnt;
__device__ float  g_sqn[6][N];
// bf16 copies of the 6 feature matrices (12 MB), natural k order.
__device__ uint32_t g_bf[6][N * D / 2];

// ---------------------------------------------------------------------------
__device__ __forceinline__ uint32_t smem_u32(const void* p) {
    uint32_t a;
    asm("{ .reg .u64 t; cvta.to.shared.u64 t, %1; cvt.u32.u64 %0, t; }" : "=r"(a) : "l"(p));
    return a;
}
__device__ __forceinline__ uint32_t pack_bf16(float lo, float hi) {
    __nv_bfloat162 v = __floats2bfloat162_rn(lo, hi);
    return *reinterpret_cast<uint32_t*>(&v);
}
__device__ __forceinline__ void mma_bf16(float* d, uint32_t a0, uint32_t a1,
                                         uint32_t a2, uint32_t a3,
                                         uint32_t b0, uint32_t b1) {
    asm volatile(
        "mma.sync.aligned.m16n8k16.row.col.f32.bf16.bf16.f32 "
        "{%0,%1,%2,%3}, {%4,%5,%6,%7}, {%8,%9}, {%0,%1,%2,%3};"
        : "+f"(d[0]), "+f"(d[1]), "+f"(d[2]), "+f"(d[3])
        : "r"(a0), "r"(a1), "r"(a2), "r"(a3), "r"(b0), "r"(b1));
}
__device__ __forceinline__ void ldmatrix_x4(uint32_t& r0, uint32_t& r1,
                                            uint32_t& r2, uint32_t& r3,
                                            uint32_t addr) {
    asm volatile("ldmatrix.sync.aligned.m8n8.x4.shared.b16 {%0,%1,%2,%3}, [%4];"
                 : "=r"(r0), "=r"(r1), "=r"(r2), "=r"(r3) : "r"(addr));
}
#define CP_ASYNC16(dst, src) \
    asm volatile("cp.async.cg.shared.global [%0], [%1], 16;" :: "r"(dst), "l"(src) : "memory")
#define CP_COMMIT() asm volatile("cp.async.commit_group;" ::: "memory")
#define CP_WAIT0()  asm volatile("cp.async.wait_group 0;" ::: "memory")

// ---------------------------------------------------------------------------
// Fused prep: bf16 conversion + row squared norms (first PREP_BLOCKS) and
// label MSE partial sums (remaining LABEL_BLOCKS). Natural k order (ldmatrix
// handles fragment layout).
__global__ void prep_kernel(const float* __restrict__ f0, const float* __restrict__ f1,
                            const float* __restrict__ f2, const float* __restrict__ f3,
                            const float* __restrict__ f4, const float* __restrict__ f5,
                            const float* __restrict__ pred,
                            const float* __restrict__ target) {
    if (blockIdx.x >= PREP_BLOCKS) {
        __shared__ float sred[256];
        const int n4 = N * C / 4;
        const int stride = LABEL_BLOCKS * 256;
        float s = 0.f;
        for (int i = (blockIdx.x - PREP_BLOCKS) * 256 + threadIdx.x; i < n4; i += stride) {
            float4 a = ((const float4*)pred)[i];
            float4 b = ((const float4*)target)[i];
            float dx = a.x - b.x, dy = a.y - b.y, dz = a.z - b.z, dw = a.w - b.w;
            s += dx * dx + dy * dy + dz * dz + dw * dw;
        }
        sred[threadIdx.x] = s;
        __syncthreads();
        for (int o = 128; o; o >>= 1) {
            if (threadIdx.x < o) sred[threadIdx.x] += sred[threadIdx.x + o];
            __syncthreads();
        }
        if (threadIdx.x == 0) atomicAdd(&g_acc[0], (double)sred[0]);
        return;
    }

    int idx = blockIdx.x * blockDim.x + threadIdx.x;   // one thread per 16-k group
    int m   = idx >> 16;
    int rem = idx & 65535;
    const float* src;
    switch (m) {
        case 0: src = f0; break; case 1: src = f1; break; case 2: src = f2; break;
        case 3: src = f3; break; case 4: src = f4; break; default: src = f5; break;
    }
    const float4* p = (const float4*)src + rem * 4;
    float4 v0 = p[0], v1 = p[1], v2 = p[2], v3 = p[3];

    float s = v0.x * v0.x + v0.y * v0.y + v0.z * v0.z + v0.w * v0.w
            + v1.x * v1.x + v1.y * v1.y + v1.z * v1.z + v1.w * v1.w
            + v2.x * v2.x + v2.y * v2.y + v2.z * v2.z + v2.w * v2.w
            + v3.x * v3.x + v3.y * v3.y + v3.z * v3.z + v3.w * v3.w;
#pragma unroll
    for (int o = 8; o; o >>= 1) s += __shfl_xor_sync(0xffffffffu, s, o);
    if ((threadIdx.x & 15) == 0) g_sqn[m][rem >> 4] = s;

    uint4 o0, o1;
    o0.x = pack_bf16(v0.x, v0.y);
    o0.y = pack_bf16(v0.z, v0.w);
    o0.z = pack_bf16(v1.x, v1.y);
    o0.w = pack_bf16(v1.z, v1.w);
    o1.x = pack_bf16(v2.x, v2.y);
    o1.y = pack_bf16(v2.z, v2.w);
    o1.z = pack_bf16(v3.x, v3.y);
    o1.w = pack_bf16(v3.z, v3.w);
    ((uint4*)&g_bf[m][(size_t)rem * 8])[0] = o0;
    ((uint4*)&g_bf[m][(size_t)rem * 8])[1] = o1;
}

// ---------------------------------------------------------------------------
// Issue one 64-k chunk of A (256 rows) + B (128 rows) into stage buffer.
__device__ __forceinline__ void issue_chunk(uint32_t sb_tiles, int buf,
                                            const uint32_t* baseA,
                                            const uint32_t* baseB, int c,
                                            int rT, int cT) {
    const uint32_t dA = sb_tiles + (uint32_t)buf * (STAGE_U * 4);
    const uint32_t dB = dA + A_TILE_U * 4;
    const uint32_t doff = (uint32_t)(rT * PITCH_U + cT * 4) * 4;
    const uint32_t rstep = 32 * PITCH_U * 4;
    const uint32_t* sA = baseA + c * 32;
    const uint32_t* sB = baseB + c * 32;
#pragma unroll
    for (int u = 0; u < 8; u++)
        CP_ASYNC16(dA + doff + u * rstep, sA + (size_t)u * 32 * (D / 2));
#pragma unroll
    for (int u = 0; u < 4; u++)
        CP_ASYNC16(dB + doff + u * rstep, sB + (size_t)u * 32 * (D / 2));
    CP_COMMIT();
}

// ---------------------------------------------------------------------------
// bf16 tensor-core fused pairwise kernel + fused finalization.
// 256x128 block tile, 8 warps (4x2), warp tile 64x64, m16n8k16, BK=64,
// fragment loads via ldmatrix.x4. Phase split with fp16-packed dP park.
__global__ void __launch_bounds__(THREADS, 1)
pair_kernel(float* __restrict__ out) {
    extern __shared__ float sm[];
    uint32_t* smu = (uint32_t*)sm;
    const uint32_t sb_tiles = smem_u32(sm + OFF_TILES);

    const int f = blockIdx.y;
    int bi2 = 0, rem = blockIdx.x;
    while (rem >= NTJ - 2 * bi2) { rem -= NTJ - 2 * bi2; bi2++; }
    const int bj = 2 * bi2 + rem;
    const bool full_tile = (bj > 2 * bi2 + 1);   // no diagonal inside

    const int tid  = threadIdx.x;
    const int wid  = tid >> 5, lane = tid & 31;
    const int wi   = wid & 3;        // row warp group (64 rows)
    const int wj   = wid >> 2;       // col warp group (64 cols)
    const int tg   = lane >> 2;
    const int q    = lane & 3;
    const int rowI = bi2 * BI, rowJ = bj * BJ;

    // Squared norms: [0:256) sqPi, [256:384) sqPj, [384:640) sqTi, [640:768) sqTj
    sm[OFF_SQ + tid]       = g_sqn[f][rowI + tid];
    sm[OFF_SQ + 384 + tid] = g_sqn[3 + f][rowI + tid];
    if (tid < 128) {
        sm[OFF_SQ + 256 + tid] = g_sqn[f][rowJ + tid];
        sm[OFF_SQ + 640 + tid] = g_sqn[3 + f][rowJ + tid];
    }

    // Staging coordinates.
    const int rT = tid >> 3;
    const int cT = tid & 7;
    const uint32_t* pA = g_bf[f]     + (size_t)(rowI + rT) * (D / 2) + cT * 4;
    const uint32_t* pB = g_bf[f]     + (size_t)(rowJ + rT) * (D / 2) + cT * 4;
    const uint32_t* tA = g_bf[3 + f] + (size_t)(rowI + rT) * (D / 2) + cT * 4;
    const uint32_t* tB = g_bf[3 + f] + (size_t)(rowJ + rT) * (D / 2) + cT * 4;

    // ldmatrix per-lane source addresses (within a stage).
    // A x4: m0=rows0-7 kLo, m1=rows8-15 kLo, m2=rows0-7 kHi, m3=rows8-15 kHi
    const uint32_t aBase = sb_tiles
        + (uint32_t)(wi * 64 + (lane & 15)) * PITCH_B + (uint32_t)(lane >> 4) * 16;
    // B x4: m0=n0-7 kLo, m1=n0-7 kHi, m2=n8-15 kLo, m3=n8-15 kHi
    const uint32_t bBase = sb_tiles + A_TILE_U * 4
        + (uint32_t)(wj * 64 + (lane & 7) + ((lane >> 4) & 1) * 8) * PITCH_B
        + (uint32_t)((lane >> 3) & 1) * 16;

    float s_total = 0.f;

    // Prologue: P chunk 0 -> buffer 0.
    issue_chunk(sb_tiles, 0, pA, pB, 0, rT, cT);

#pragma unroll 1
    for (int phase = 0; phase < 2; ++phase) {
        const uint32_t* cA = phase ? tA : pA;
        const uint32_t* cB = phase ? tB : pB;

        float acc[4][8][4];
#pragma unroll
        for (int mt = 0; mt < 4; mt++)
#pragma unroll
            for (int nt = 0; nt < 8; nt++)
#pragma unroll
                for (int e = 0; e < 4; e++) acc[mt][nt][e] = 0.f;

#pragma unroll 1
        for (int c = 0; c < NCHUNK; c++) {
            CP_WAIT0();
            __syncthreads();

            // Prefetch next chunk (or phase-1 chunk 0, overlapping epilogue).
            if (c + 1 < NCHUNK)
                issue_chunk(sb_tiles, (c + 1) & 1, cA, cB, c + 1, rT, cT);
            else if (phase == 0)
                issue_chunk(sb_tiles, 0, tA, tB, 0, rT, cT);

            const uint32_t so = (uint32_t)(c & 1) * (STAGE_U * 4);
#pragma unroll
            for (int g = 0; g < 4; g++) {
                uint32_t a0[4], a1[4], a2[4], a3[4], b0[8], b1[8];
#pragma unroll
                for (int mt = 0; mt < 4; mt++)
                    ldmatrix_x4(a0[mt], a1[mt], a2[mt], a3[mt],
                                aBase + so + (uint32_t)mt * (16 * PITCH_B) + g * 32);
#pragma unroll
                for (int pp = 0; pp < 4; pp++)
                    ldmatrix_x4(b0[2 * pp], b1[2 * pp], b0[2 * pp + 1], b1[2 * pp + 1],
                                bBase + so + (uint32_t)pp * (16 * PITCH_B) + g * 32);
#pragma unroll
                for (int mt = 0; mt < 4; mt++)
#pragma unroll
                    for (int nt = 0; nt < 8; nt++)
                        mma_bf16(acc[mt][nt], a0[mt], a1[mt], a2[mt], a3[mt],
                                 b0[nt], b1[nt]);
            }
        }

        // Epilogue. Hoist sqn values into registers.
        const float* sqi = sm + OFF_SQ + phase * 384;
        const float* sqj = sqi + 256;
        float sqi_r[4][2], sqj_r[8][2];
#pragma unroll
        for (int mt = 0; mt < 4; mt++) {
            sqi_r[mt][0] = sqi[wi * 64 + mt * 16 + tg];
            sqi_r[mt][1] = sqi[wi * 64 + mt * 16 + tg + 8];
        }
#pragma unroll
        for (int nt = 0; nt < 8; nt++) {
            sqj_r[nt][0] = sqj[wj * 64 + nt * 8 + 2 * q];
            sqj_r[nt][1] = sqj[wj * 64 + nt * 8 + 2 * q + 1];
        }

        if (phase == 0) {
#pragma unroll
            for (int mt = 0; mt < 4; mt++)
#pragma unroll
                for (int nt = 0; nt < 8; nt++)
#pragma unroll
                    for (int pi = 0; pi < 2; pi++) {
                        float2 dd;
                        float sq0 = sqi_r[mt][pi] + sqj_r[nt][0] - 2.f * acc[mt][nt][pi * 2];
                        float sq1 = sqi_r[mt][pi] + sqj_r[nt][1] - 2.f * acc[mt][nt][pi * 2 + 1];
                        dd.x = sq0 > 0.f ? sq0 * rsqrtf(sq0) : 0.f;
                        dd.y = sq1 > 0.f ? sq1 * rsqrtf(sq1) : 0.f;
                        __half2 h = __float22half2_rn(dd);
                        smu[OFF_DPH + ((mt * 8 + nt) * 2 + pi) * THREADS + tid] =
                            *reinterpret_cast<uint32_t*>(&h);
                    }
        } else if (full_tile) {
#pragma unroll
            for (int mt = 0; mt < 4; mt++)
#pragma unroll
                for (int nt = 0; nt < 8; nt++)
#pragma unroll
                    for (int pi = 0; pi < 2; pi++) {
                        float sq0 = sqi_r[mt][pi] + sqj_r[nt][0] - 2.f * acc[mt][nt][pi * 2];
                        float sq1 = sqi_r[mt][pi] + sqj_r[nt][1] - 2.f * acc[mt][nt][pi * 2 + 1];
                        float dt0 = sq0 > 0.f ? sq0 * rsqrtf(sq0) : 0.f;
                        float dt1 = sq1 > 0.f ? sq1 * rsqrtf(sq1) : 0.f;
                        uint32_t pk = smu[OFF_DPH + ((mt * 8 + nt) * 2 + pi) * THREADS + tid];
                        float2 dp = __half22float2(*reinterpret_cast<__half2*>(&pk));
                        float d0 = dp.x - dt0, d1 = dp.y - dt1;
                        s_total += d0 * d0 + d1 * d1;
                    }
            s_total *= 2.f;
        } else {
#pragma unroll
            for (int mt = 0; mt < 4; mt++)
#pragma unroll
                for (int nt = 0; nt < 8; nt++)
#pragma unroll
                    for (int pi = 0; pi < 2; pi++) {
                        int gi = rowI + wi * 64 + mt * 16 + tg + pi * 8;
                        int gj = rowJ + wj * 64 + nt * 8 + 2 * q;
                        float sq0 = sqi_r[mt][pi] + sqj_r[nt][0] - 2.f * acc[mt][nt][pi * 2];
                        float sq1 = sqi_r[mt][pi] + sqj_r[nt][1] - 2.f * acc[mt][nt][pi * 2 + 1];
                        float dt0 = sq0 > 0.f ? sq0 * rsqrtf(sq0) : 0.f;
                        float dt1 = sq1 > 0.f ? sq1 * rsqrtf(sq1) : 0.f;
                        uint32_t pk = smu[OFF_DPH + ((mt * 8 + nt) * 2 + pi) * THREADS + tid];
                        float2 dp = __half22float2(*reinterpret_cast<__half2*>(&pk));
                        float d0 = dp.x - dt0, d1 = dp.y - dt1;
                        s_total += (gj > gi ? 2.f : 0.f) * d0 * d0;
                        s_total += (gj + 1 > gi ? 2.f : 0.f) * d1 * d1;
                    }
        }
    }

#pragma unroll
    for (int o = 16; o; o >>= 1) s_total += __shfl_xor_sync(0xffffffffu, s_total, o);
    if (lane == 0) sm[OFF_SRED + wid] = s_total;
    __syncthreads();
    if (tid == 0) {
        double tot = 0.0;
#pragma unroll
        for (int w = 0; w < 8; w++) tot += (double)sm[OFF_SRED + w];
        atomicAdd(&g_acc[1 + f], tot);

        __threadfence();
        unsigned int t = atomicAdd(&g_cnt, 1u);
        if (t == 3 * NTILES - 1) {
            double label = g_acc[0] / ((double)N * (double)C);
            double feat  = (g_acc[1] + g_acc[2] + g_acc[3]) / ((double)N * (double)N);
            out[0] = (float)((1.0 - 0.8) * label + 0.8 * feat / 3.0);
            g_acc[0] = 0.0; g_acc[1] = 0.0; g_acc[2] = 0.0; g_acc[3] = 0.0;
            g_cnt = 0u;
        }
    }
}

// ---------------------------------------------------------------------------
extern "C" void kernel_launch(void* const* d_in, const int* in_sizes, int n_in,
                              void* d_out, int out_size) {
    const float* pred   = (const float*)d_in[0];
    const float* target = (const float*)d_in[1];
    const float* pf0 = (const float*)d_in[2];
    const float* pf1 = (const float*)d_in[3];
    const float* pf2 = (const float*)d_in[4];
    const float* tf0 = (const float*)d_in[5];
    const float* tf1 = (const float*)d_in[6];
    const float* tf2 = (const float*)d_in[7];
    float* out = (float*)d_out;

    static int configured = 0;
    if (!configured) {
        cudaFuncSetAttribute(pair_kernel,
                             cudaFuncAttributeMaxDynamicSharedMemorySize, SMEM_BYTES);
        configured = 1;
    }

    prep_kernel<<<PREP_BLOCKS + LABEL_BLOCKS, 256>>>(pf0, pf1, pf2, tf0, tf1, tf2,
                                                     pred, target);

    dim3 grid(NTILES, 3);
    pair_kernel<<<grid, THREADS, SMEM_BYTES>>>(out);
}

// round 17
// speedup vs baseline: 1.2175x; 1.2175x over previous
#include <cuda_runtime.h>
#include <cuda_bf16.h>
#include <cuda_fp16.h>
#include <cstdint>

#define N 4096
#define D 256
#define C 1000
#define BM 128
#define NT (N / BM)                 // 32
#define NTILES (NT * (NT + 1) / 2)  // 528
#define NCHUNK 4                    // 4 chunks of 64 k per phase
#define THREADS 128

#define PREP_BLOCKS (6 * N * D / 16 / 256)   // 6144
#define LABEL_BLOCKS 512

#define PITCH_U 36                  // u32 per smem tile row (32 data + 4 pad)
#define PITCH_B (PITCH_U * 4)       // 144 bytes
#define TILE_U (BM * PITCH_U)       // 4608 u32 per operand tile
#define STAGE_U (2 * TILE_U)        // A + B

// Shared memory layout (32-bit words)
#define OFF_DPH   0                           // 64*128 u32 (dP parked as f16x2)
#define OFF_TILES 8192                        // 2 stages x (A+B) = 18432 u32
#define OFF_SQ    (OFF_TILES + 2 * STAGE_U)   // 512 f32
#define OFF_SRED  (OFF_SQ + 512)
#define SMEM_WORDS (OFF_SRED + 4)
#define SMEM_BYTES (SMEM_WORDS * 4)           // 108,560 B  (2 CTAs/SM fit)

// Persistent device state; zero at the start of every call (static zero-init;
// the finishing pair block resets after producing the output).
__device__ double g_acc[4];
__device__ unsigned int g_cnt;
__device__ float  g_sqn[6][N];
// bf16 copies of the 6 feature matrices (12 MB), natural k order.
__device__ uint32_t g_bf[6][N * D / 2];

// ---------------------------------------------------------------------------
__device__ __forceinline__ uint32_t smem_u32(const void* p) {
    uint32_t a;
    asm("{ .reg .u64 t; cvta.to.shared.u64 t, %1; cvt.u32.u64 %0, t; }" : "=r"(a) : "l"(p));
    return a;
}
__device__ __forceinline__ uint32_t pack_bf16(float lo, float hi) {
    __nv_bfloat162 v = __floats2bfloat162_rn(lo, hi);
    return *reinterpret_cast<uint32_t*>(&v);
}
__device__ __forceinline__ void mma_bf16(float* d, uint32_t a0, uint32_t a1,
                                         uint32_t a2, uint32_t a3,
                                         uint32_t b0, uint32_t b1) {
    asm volatile(
        "mma.sync.aligned.m16n8k16.row.col.f32.bf16.bf16.f32 "
        "{%0,%1,%2,%3}, {%4,%5,%6,%7}, {%8,%9}, {%0,%1,%2,%3};"
        : "+f"(d[0]), "+f"(d[1]), "+f"(d[2]), "+f"(d[3])
        : "r"(a0), "r"(a1), "r"(a2), "r"(a3), "r"(b0), "r"(b1));
}
__device__ __forceinline__ void ldmatrix_x4(uint32_t& r0, uint32_t& r1,
                                            uint32_t& r2, uint32_t& r3,
                                            uint32_t addr) {
    asm volatile("ldmatrix.sync.aligned.m8n8.x4.shared.b16 {%0,%1,%2,%3}, [%4];"
                 : "=r"(r0), "=r"(r1), "=r"(r2), "=r"(r3) : "r"(addr));
}
#define CP_ASYNC16(dst, src) \
    asm volatile("cp.async.cg.shared.global [%0], [%1], 16;" :: "r"(dst), "l"(src) : "memory")
#define CP_COMMIT() asm volatile("cp.async.commit_group;" ::: "memory")
#define CP_WAIT0()  asm volatile("cp.async.wait_group 0;" ::: "memory")

// ---------------------------------------------------------------------------
// Fused prep: bf16 conversion + row squared norms (first PREP_BLOCKS) and
// label MSE partial sums (remaining LABEL_BLOCKS). Natural k order.
__global__ void prep_kernel(const float* __restrict__ f0, const float* __restrict__ f1,
                            const float* __restrict__ f2, const float* __restrict__ f3,
                            const float* __restrict__ f4, const float* __restrict__ f5,
                            const float* __restrict__ pred,
                            const float* __restrict__ target) {
    if (blockIdx.x >= PREP_BLOCKS) {
        __shared__ float sred[256];
        const int n4 = N * C / 4;
        const int stride = LABEL_BLOCKS * 256;
        float s = 0.f;
        for (int i = (blockIdx.x - PREP_BLOCKS) * 256 + threadIdx.x; i < n4; i += stride) {
            float4 a = ((const float4*)pred)[i];
            float4 b = ((const float4*)target)[i];
            float dx = a.x - b.x, dy = a.y - b.y, dz = a.z - b.z, dw = a.w - b.w;
            s += dx * dx + dy * dy + dz * dz + dw * dw;
        }
        sred[threadIdx.x] = s;
        __syncthreads();
        for (int o = 128; o; o >>= 1) {
            if (threadIdx.x < o) sred[threadIdx.x] += sred[threadIdx.x + o];
            __syncthreads();
        }
        if (threadIdx.x == 0) atomicAdd(&g_acc[0], (double)sred[0]);
        return;
    }

    int idx = blockIdx.x * blockDim.x + threadIdx.x;   // one thread per 16-k group
    int m   = idx >> 16;
    int rem = idx & 65535;
    const float* src;
    switch (m) {
        case 0: src = f0; break; case 1: src = f1; break; case 2: src = f2; break;
        case 3: src = f3; break; case 4: src = f4; break; default: src = f5; break;
    }
    const float4* p = (const float4*)src + rem * 4;
    float4 v0 = p[0], v1 = p[1], v2 = p[2], v3 = p[3];

    float s = v0.x * v0.x + v0.y * v0.y + v0.z * v0.z + v0.w * v0.w
            + v1.x * v1.x + v1.y * v1.y + v1.z * v1.z + v1.w * v1.w
            + v2.x * v2.x + v2.y * v2.y + v2.z * v2.z + v2.w * v2.w
            + v3.x * v3.x + v3.y * v3.y + v3.z * v3.z + v3.w * v3.w;
#pragma unroll
    for (int o = 8; o; o >>= 1) s += __shfl_xor_sync(0xffffffffu, s, o);
    if ((threadIdx.x & 15) == 0) g_sqn[m][rem >> 4] = s;

    uint4 o0, o1;
    o0.x = pack_bf16(v0.x, v0.y);
    o0.y = pack_bf16(v0.z, v0.w);
    o0.z = pack_bf16(v1.x, v1.y);
    o0.w = pack_bf16(v1.z, v1.w);
    o1.x = pack_bf16(v2.x, v2.y);
    o1.y = pack_bf16(v2.z, v2.w);
    o1.z = pack_bf16(v3.x, v3.y);
    o1.w = pack_bf16(v3.z, v3.w);
    ((uint4*)&g_bf[m][(size_t)rem * 8])[0] = o0;
    ((uint4*)&g_bf[m][(size_t)rem * 8])[1] = o1;
}

// ---------------------------------------------------------------------------
// Issue one 64-k chunk of A (128 rows) + B (128 rows) into a stage buffer.
// 128 threads x 16 cp.async x 16B. rT = tid>>3 (row base), cT = tid&7.
__device__ __forceinline__ void issue_chunk(uint32_t sb_tiles, int buf,
                                            const uint32_t* baseA,
                                            const uint32_t* baseB, int c,
                                            int rT, int cT) {
    const uint32_t dA = sb_tiles + (uint32_t)buf * (STAGE_U * 4);
    const uint32_t dB = dA + TILE_U * 4;
    const uint32_t doff = (uint32_t)(rT * PITCH_U + cT * 4) * 4;
    const uint32_t rstep = 16 * PITCH_U * 4;
    const uint32_t* sA = baseA + c * 32;
    const uint32_t* sB = baseB + c * 32;
#pragma unroll
    for (int u = 0; u < 8; u++)
        CP_ASYNC16(dA + doff + u * rstep, sA + (size_t)u * 16 * (D / 2));
#pragma unroll
    for (int u = 0; u < 8; u++)
        CP_ASYNC16(dB + doff + u * rstep, sB + (size_t)u * 16 * (D / 2));
    CP_COMMIT();
}

// ---------------------------------------------------------------------------
// bf16 tensor-core fused pairwise kernel + fused finalization.
// 128x128 block tile, 4 warps (2x2), warp tile 64x64, m16n8k16, BK=64,
// ldmatrix fragment loads, fp16-packed dP park. 2 CTAs per SM.
__global__ void __launch_bounds__(THREADS, 2)
pair_kernel(float* __restrict__ out) {
    extern __shared__ float sm[];
    uint32_t* smu = (uint32_t*)sm;
    const uint32_t sb_tiles = smem_u32(sm + OFF_TILES);

    const int f = blockIdx.y;
    int bi = 0, rem = blockIdx.x;
    while (rem >= NT - bi) { rem -= NT - bi; bi++; }
    const int bj = bi + rem;
    const bool full_tile = (bj > bi);   // diagonal only when bi == bj

    const int tid  = threadIdx.x;
    const int wid  = tid >> 5, lane = tid & 31;
    const int wi   = wid & 1;        // row warp group (64 rows)
    const int wj   = wid >> 1;       // col warp group (64 cols)
    const int tg   = lane >> 2;
    const int q    = lane & 3;
    const int rowI = bi * BM, rowJ = bj * BM;

    // Squared norms: [0:128) sqPi, [128:256) sqPj, [256:384) sqTi, [384:512) sqTj
    sm[OFF_SQ + tid]       = g_sqn[f][rowI + tid];
    sm[OFF_SQ + 128 + tid] = g_sqn[f][rowJ + tid];
    sm[OFF_SQ + 256 + tid] = g_sqn[3 + f][rowI + tid];
    sm[OFF_SQ + 384 + tid] = g_sqn[3 + f][rowJ + tid];

    // Staging coordinates.
    const int rT = tid >> 3;        // 0..15
    const int cT = tid & 7;
    const uint32_t* pA = g_bf[f]     + (size_t)(rowI + rT) * (D / 2) + cT * 4;
    const uint32_t* pB = g_bf[f]     + (size_t)(rowJ + rT) * (D / 2) + cT * 4;
    const uint32_t* tA = g_bf[3 + f] + (size_t)(rowI + rT) * (D / 2) + cT * 4;
    const uint32_t* tB = g_bf[3 + f] + (size_t)(rowJ + rT) * (D / 2) + cT * 4;

    // ldmatrix per-lane source addresses (within a stage).
    const uint32_t aBase = sb_tiles
        + (uint32_t)(wi * 64 + (lane & 15)) * PITCH_B + (uint32_t)(lane >> 4) * 16;
    const uint32_t bBase = sb_tiles + TILE_U * 4
        + (uint32_t)(wj * 64 + (lane & 7) + ((lane >> 4) & 1) * 8) * PITCH_B
        + (uint32_t)((lane >> 3) & 1) * 16;

    float s_total = 0.f;

    // Prologue: P chunk 0 -> buffer 0.
    issue_chunk(sb_tiles, 0, pA, pB, 0, rT, cT);

#pragma unroll 1
    for (int phase = 0; phase < 2; ++phase) {
        const uint32_t* cA = phase ? tA : pA;
        const uint32_t* cB = phase ? tB : pB;

        float acc[4][8][4];
#pragma unroll
        for (int mt = 0; mt < 4; mt++)
#pragma unroll
            for (int nt = 0; nt < 8; nt++)
#pragma unroll
                for (int e = 0; e < 4; e++) acc[mt][nt][e] = 0.f;

#pragma unroll 1
        for (int c = 0; c < NCHUNK; c++) {
            CP_WAIT0();
            __syncthreads();

            // Prefetch next chunk (or phase-1 chunk 0, overlapping epilogue).
            if (c + 1 < NCHUNK)
                issue_chunk(sb_tiles, (c + 1) & 1, cA, cB, c + 1, rT, cT);
            else if (phase == 0)
                issue_chunk(sb_tiles, 0, tA, tB, 0, rT, cT);

            const uint32_t so = (uint32_t)(c & 1) * (STAGE_U * 4);
#pragma unroll
            for (int g = 0; g < 4; g++) {
                uint32_t a0[4], a1[4], a2[4], a3[4], b0[8], b1[8];
#pragma unroll
                for (int mt = 0; mt < 4; mt++)
                    ldmatrix_x4(a0[mt], a1[mt], a2[mt], a3[mt],
                                aBase + so + (uint32_t)mt * (16 * PITCH_B) + g * 32);
#pragma unroll
                for (int pp = 0; pp < 4; pp++)
                    ldmatrix_x4(b0[2 * pp], b1[2 * pp], b0[2 * pp + 1], b1[2 * pp + 1],
                                bBase + so + (uint32_t)pp * (16 * PITCH_B) + g * 32);
#pragma unroll
                for (int mt = 0; mt < 4; mt++)
#pragma unroll
                    for (int nt = 0; nt < 8; nt++)
                        mma_bf16(acc[mt][nt], a0[mt], a1[mt], a2[mt], a3[mt],
                                 b0[nt], b1[nt]);
            }
        }

        // Epilogue. Hoist sqn values into registers.
        const float* sqi = sm + OFF_SQ + phase * 256;
        const float* sqj = sqi + 128;
        float sqi_r[4][2], sqj_r[8][2];
#pragma unroll
        for (int mt = 0; mt < 4; mt++) {
            sqi_r[mt][0] = sqi[wi * 64 + mt * 16 + tg];
            sqi_r[mt][1] = sqi[wi * 64 + mt * 16 + tg + 8];
        }
#pragma unroll
        for (int nt = 0; nt < 8; nt++) {
            sqj_r[nt][0] = sqj[wj * 64 + nt * 8 + 2 * q];
            sqj_r[nt][1] = sqj[wj * 64 + nt * 8 + 2 * q + 1];
        }

        if (phase == 0) {
#pragma unroll
            for (int mt = 0; mt < 4; mt++)
#pragma unroll
                for (int nt = 0; nt < 8; nt++)
#pragma unroll
                    for (int pi = 0; pi < 2; pi++) {
                        float2 dd;
                        float sq0 = sqi_r[mt][pi] + sqj_r[nt][0] - 2.f * acc[mt][nt][pi * 2];
                        float sq1 = sqi_r[mt][pi] + sqj_r[nt][1] - 2.f * acc[mt][nt][pi * 2 + 1];
                        dd.x = sq0 > 0.f ? sq0 * rsqrtf(sq0) : 0.f;
                        dd.y = sq1 > 0.f ? sq1 * rsqrtf(sq1) : 0.f;
                        __half2 h = __float22half2_rn(dd);
                        smu[OFF_DPH + ((mt * 8 + nt) * 2 + pi) * THREADS + tid] =
                            *reinterpret_cast<uint32_t*>(&h);
                    }
        } else if (full_tile) {
#pragma unroll
            for (int mt = 0; mt < 4; mt++)
#pragma unroll
                for (int nt = 0; nt < 8; nt++)
#pragma unroll
                    for (int pi = 0; pi < 2; pi++) {
                        float sq0 = sqi_r[mt][pi] + sqj_r[nt][0] - 2.f * acc[mt][nt][pi * 2];
                        float sq1 = sqi_r[mt][pi] + sqj_r[nt][1] - 2.f * acc[mt][nt][pi * 2 + 1];
                        float dt0 = sq0 > 0.f ? sq0 * rsqrtf(sq0) : 0.f;
                        float dt1 = sq1 > 0.f ? sq1 * rsqrtf(sq1) : 0.f;
                        uint32_t pk = smu[OFF_DPH + ((mt * 8 + nt) * 2 + pi) * THREADS + tid];
                        float2 dp = __half22float2(*reinterpret_cast<__half2*>(&pk));
                        float d0 = dp.x - dt0, d1 = dp.y - dt1;
                        s_total += d0 * d0 + d1 * d1;
                    }
            s_total *= 2.f;
        } else {
            // Diagonal tile: per-element weight {0,2}; diag itself = 0.
#pragma unroll
            for (int mt = 0; mt < 4; mt++)
#pragma unroll
                for (int nt = 0; nt < 8; nt++)
#pragma unroll
                    for (int pi = 0; pi < 2; pi++) {
                        int gi = wi * 64 + mt * 16 + tg + pi * 8;
                        int gj = wj * 64 + nt * 8 + 2 * q;
                        float sq0 = sqi_r[mt][pi] + sqj_r[nt][0] - 2.f * acc[mt][nt][pi * 2];
                        float sq1 = sqi_r[mt][pi] + sqj_r[nt][1] - 2.f * acc[mt][nt][pi * 2 + 1];
                        float dt0 = sq0 > 0.f ? sq0 * rsqrtf(sq0) : 0.f;
                        float dt1 = sq1 > 0.f ? sq1 * rsqrtf(sq1) : 0.f;
                        uint32_t pk = smu[OFF_DPH + ((mt * 8 + nt) * 2 + pi) * THREADS + tid];
                        float2 dp = __half22float2(*reinterpret_cast<__half2*>(&pk));
                        float d0 = dp.x - dt0, d1 = dp.y - dt1;
                        s_total += (gj > gi ? 2.f : 0.f) * d0 * d0;
                        s_total += (gj + 1 > gi ? 2.f : 0.f) * d1 * d1;
                    }
        }
    }

#pragma unroll
    for (int o = 16; o; o >>= 1) s_total += __shfl_xor_sync(0xffffffffu, s_total, o);
    if (lane == 0) sm[OFF_SRED + wid] = s_total;
    __syncthreads();
    if (tid == 0) {
        double tot = (double)sm[OFF_SRED] + (double)sm[OFF_SRED + 1]
                   + (double)sm[OFF_SRED + 2] + (double)sm[OFF_SRED + 3];
        atomicAdd(&g_acc[1 + f], tot);

        __threadfence();
        unsigned int t = atomicAdd(&g_cnt, 1u);
        if (t == 3 * NTILES - 1) {
            double label = g_acc[0] / ((double)N * (double)C);
            double feat  = (g_acc[1] + g_acc[2] + g_acc[3]) / ((double)N * (double)N);
            out[0] = (float)((1.0 - 0.8) * label + 0.8 * feat / 3.0);
            g_acc[0] = 0.0; g_acc[1] = 0.0; g_acc[2] = 0.0; g_acc[3] = 0.0;
            g_cnt = 0u;
        }
    }
}

// ---------------------------------------------------------------------------
extern "C" void kernel_launch(void* const* d_in, const int* in_sizes, int n_in,
                              void* d_out, int out_size) {
    const float* pred   = (const float*)d_in[0];
    const float* target = (const float*)d_in[1];
    const float* pf0 = (const float*)d_in[2];
    const float* pf1 = (const float*)d_in[3];
    const float* pf2 = (const float*)d_in[4];
    const float* tf0 = (const float*)d_in[5];
    const float* tf1 = (const float*)d_in[6];
    const float* tf2 = (const float*)d_in[7];
    float* out = (float*)d_out;

    static int configured = 0;
    if (!configured) {
        cudaFuncSetAttribute(pair_kernel,
                             cudaFuncAttributeMaxDynamicSharedMemorySize, SMEM_BYTES);
        configured = 1;
    }

    prep_kernel<<<PREP_BLOCKS + LABEL_BLOCKS, 256>>>(pf0, pf1, pf2, tf0, tf1, tf2,
                                                     pred, target);

    dim3 grid(NTILES, 3);
    pair_kernel<<<grid, THREADS, SMEM_BYTES>>>(out);
}